// round 1
// baseline (speedup 1.0000x reference)
#include <cuda_runtime.h>
#include <cuda_bf16.h>
#include <math.h>

#define NB 4
#define NTOK 2048
#define NATOMS 16384
#define CATOM 128
#define CTOK 384
#define CPAIR 16
#define NQ 32
#define NKEY 128
#define NHEADS 4
#define DH 32
#define NWIN (NATOMS / NQ)   // 512
#define PAD 48

// ---------------- scratch (static device globals; no allocation) -------------
__device__ float g_x[NB * NATOMS * CATOM];
__device__ float g_h[NB * NATOMS * CATOM];
__device__ float g_q[NB * NATOMS * CATOM];
__device__ float g_k[NB * NATOMS * CATOM];
__device__ float g_v[NB * NATOMS * CATOM];
__device__ float g_o[NB * NATOMS * CATOM];
__device__ float g_hid[NB * NATOMS * 512];
__device__ float g_atok[NB * NTOK * CATOM];
__device__ float g_bias[NB * NHEADS * NQ * NKEY];

// ---------------- generic SGEMM: C = [relu]( A[M,K] @ B[K,N] ) [+ Cin] -------
// BM=BN=64, BK=16, 256 threads, 4x4 register tile per thread.
// flags: bit0 = relu, bit1 = add Cin
__global__ void sgemm_kernel(const float* __restrict__ A, const float* __restrict__ B,
                             const float* __restrict__ Cin, float* __restrict__ C,
                             int M, int N, int K, int flags) {
    __shared__ float As[16][65];
    __shared__ float Bs[16][64];
    int tid = threadIdx.x;
    int tx = tid & 15, ty = tid >> 4;
    int bx = blockIdx.x, by = blockIdx.y;
    const float* Ablk = A + (size_t)by * 64 * K;
    const float* Bblk = B + (size_t)bx * 64;
    float acc[4][4] = {};
    int ka = tid & 15, ma = tid >> 4;
    int nb = tid & 63, kb = tid >> 6;
    for (int kt = 0; kt < K; kt += 16) {
#pragma unroll
        for (int p = 0; p < 4; p++)
            As[ka][ma + 16 * p] = Ablk[(size_t)(ma + 16 * p) * K + kt + ka];
#pragma unroll
        for (int p = 0; p < 4; p++)
            Bs[kb + 4 * p][nb] = Bblk[(size_t)(kt + kb + 4 * p) * N + nb];
        __syncthreads();
#pragma unroll
        for (int kk = 0; kk < 16; kk++) {
            float af[4], bf[4];
#pragma unroll
            for (int i = 0; i < 4; i++) af[i] = As[kk][ty + 16 * i];
#pragma unroll
            for (int j = 0; j < 4; j++) bf[j] = Bs[kk][tx + 16 * j];
#pragma unroll
            for (int i = 0; i < 4; i++)
#pragma unroll
                for (int j = 0; j < 4; j++)
                    acc[i][j] += af[i] * bf[j];
        }
        __syncthreads();
    }
#pragma unroll
    for (int i = 0; i < 4; i++) {
        int r = by * 64 + ty + 16 * i;
#pragma unroll
        for (int j = 0; j < 4; j++) {
            int c = bx * 64 + tx + 16 * j;
            float val = acc[i][j];
            if (flags & 1) val = fmaxf(val, 0.f);
            size_t idx = (size_t)r * N + c;
            if (flags & 2) val += Cin[idx];
            C[idx] = val;
        }
    }
}

// ---------------- gather token features to atoms -----------------------------
__global__ void gather_kernel(const float* __restrict__ atok, const int* __restrict__ idx,
                              float* __restrict__ x) {
    size_t i = (size_t)blockIdx.x * blockDim.x + threadIdx.x;
    if (i >= (size_t)NB * NATOMS * CATOM) return;
    int c = (int)(i & 127);
    size_t n = i >> 7;
    int b = (int)(n >> 14);
    int atom = (int)(n & (NATOMS - 1));
    int tok = idx[(size_t)b * NATOMS + atom];
    x[i] = atok[((size_t)b * NTOK + tok) * CATOM + c];
}

// ---------------- layernorm: out = (x-m)*rsqrt(var+eps)*g + b ----------------
__global__ void ln_kernel(const float* __restrict__ x, float* __restrict__ out,
                          const float* __restrict__ g, const float* __restrict__ b) {
    int row = blockIdx.x;
    int t = threadIdx.x;  // 128
    float v = x[(size_t)row * 128 + t];
    __shared__ float red[8];
    float s = v, s2 = v * v;
    for (int o = 16; o > 0; o >>= 1) {
        s += __shfl_down_sync(0xffffffff, s, o);
        s2 += __shfl_down_sync(0xffffffff, s2, o);
    }
    int w = t >> 5;
    if ((t & 31) == 0) { red[w] = s; red[4 + w] = s2; }
    __syncthreads();
    if (t == 0) {
        float ts = red[0] + red[1] + red[2] + red[3];
        float t2 = red[4] + red[5] + red[6] + red[7];
        red[0] = ts * (1.f / 128.f);
        red[4] = t2 * (1.f / 128.f);
    }
    __syncthreads();
    float mean = red[0];
    float var = red[4] - mean * mean;
    float rs = rsqrtf(var + 1e-5f);
    out[(size_t)row * 128 + t] = (v - mean) * rs * g[t] + b[t];
}

// ---------------- pair embedding + attention bias ----------------------------
// Only atoms [0,128) per batch contribute. One block per batch, 128 threads.
__global__ void pair_kernel(const float* __restrict__ x,
                            const float* __restrict__ Wcl, const float* __restrict__ Wcm,
                            const float* __restrict__ Wm1, const float* __restrict__ Wm2,
                            const float* __restrict__ Wpb, float* __restrict__ bias) {
    int b = blockIdx.x;
    int t = threadIdx.x;  // 128
    __shared__ float Wsum[128][16];
    __shared__ float m1[16][16], m2[16][16], pb[16][4];
    __shared__ float p_s[128][17];
    for (int e = t; e < 128 * 16; e += 128) Wsum[e >> 4][e & 15] = Wcl[e] + Wcm[e];
    if (t < 256 - 128) {}  // no-op to keep structure simple
    if (t < 128) {
        if (t < 16 * 16) { m1[t >> 4][t & 15] = Wm1[t]; m2[t >> 4][t & 15] = Wm2[t]; }
        if (t < 64) pb[t >> 2][t & 3] = Wpb[t];
    }
    __syncthreads();
    const float* xr = x + ((size_t)b * NATOMS + t) * 128;
    float t0[16], t1[16];
    for (int c = 0; c < 16; c++) {
        float s = 0.f;
        for (int kk = 0; kk < 128; kk++) s += xr[kk] * Wsum[kk][c];
        t0[c] = s;
    }
    for (int c = 0; c < 16; c++) {
        float s = 0.f;
#pragma unroll
        for (int kk = 0; kk < 16; kk++) s += fmaxf(t0[kk], 0.f) * m1[kk][c];
        t1[c] = s;
    }
    for (int c = 0; c < 16; c++) {
        float s = 0.f;
#pragma unroll
        for (int kk = 0; kk < 16; kk++) s += fmaxf(t1[kk], 0.f) * m2[kk][c];
        p_s[t][c] = s;
    }
    __syncthreads();
    for (int e = t; e < NHEADS * NQ * NKEY; e += 128) {
        int h = e >> 12;
        int qk = e & 4095;
        int qi = qk >> 7, j = qk & 127;
        float s = 0.f;
#pragma unroll
        for (int c = 0; c < 16; c++) s += (p_s[qi][c] + p_s[j][c]) * pb[c][h];
        bias[((size_t)b * NHEADS + h) * 4096 + qk] = s;
    }
}

// ---------------- windowed attention -----------------------------------------
// One block per (b, window), 256 threads, loops over 4 heads.
__global__ void attn_kernel(const float* __restrict__ q, const float* __restrict__ k,
                            const float* __restrict__ v, const float* __restrict__ bias,
                            float* __restrict__ o) {
    int bw = blockIdx.x;
    int b = bw >> 9, w = bw & (NWIN - 1);
    int tid = threadIdx.x;  // 256
    __shared__ float q_s[32][33];
    __shared__ float kv_s[128][33];
    __shared__ float sc[32][128];
    const float scale = 0.17677669529663687f;  // 1/sqrt(32)
    size_t base = (size_t)b * NATOMS * 128;
    int a0 = w * 32 - PAD;
    for (int h = 0; h < NHEADS; h++) {
        for (int e = tid; e < 32 * 32; e += 256) {
            int qi = e >> 5, d = e & 31;
            q_s[qi][d] = q[base + (size_t)(w * 32 + qi) * 128 + h * 32 + d];
        }
        for (int e = tid; e < 128 * 32; e += 256) {
            int j = e >> 5, d = e & 31;
            int a = a0 + j;
            kv_s[j][d] = (a >= 0 && a < NATOMS) ? k[base + (size_t)a * 128 + h * 32 + d] : 0.f;
        }
        __syncthreads();
        {
            int qi = tid >> 3, g = tid & 7;
            const float* brow = bias + (((size_t)b * NHEADS + h) * 32 + qi) * 128;
            for (int j = g * 16; j < g * 16 + 16; j++) {
                float s = 0.f;
#pragma unroll
                for (int d = 0; d < 32; d++) s += q_s[qi][d] * kv_s[j][d];
                int a = a0 + j;
                s = s * scale + brow[j];
                if (a < 0 || a >= NATOMS) s = -1e9f;
                sc[qi][j] = s;
            }
        }
        __syncthreads();
        if (tid < 32) {
            float m = -1e30f;
            for (int j = 0; j < 128; j++) m = fmaxf(m, sc[tid][j]);
            float sum = 0.f;
            for (int j = 0; j < 128; j++) {
                float e = expf(sc[tid][j] - m);
                sc[tid][j] = e;
                sum += e;
            }
            float inv = 1.f / sum;
            for (int j = 0; j < 128; j++) sc[tid][j] *= inv;
        }
        __syncthreads();
        for (int e = tid; e < 128 * 32; e += 256) {
            int j = e >> 5, d = e & 31;
            int a = a0 + j;
            kv_s[j][d] = (a >= 0 && a < NATOMS) ? v[base + (size_t)a * 128 + h * 32 + d] : 0.f;
        }
        __syncthreads();
        {
            int qi = tid >> 3, g = tid & 7;
            float acc[4] = {0.f, 0.f, 0.f, 0.f};
            for (int j = 0; j < 128; j++) {
                float p = sc[qi][j];
#pragma unroll
                for (int dd = 0; dd < 4; dd++) acc[dd] += p * kv_s[j][g * 4 + dd];
            }
#pragma unroll
            for (int dd = 0; dd < 4; dd++)
                o[base + (size_t)(w * 32 + qi) * 128 + h * 32 + g * 4 + dd] = acc[dd];
        }
        __syncthreads();
    }
}

// ---------------- host orchestration -----------------------------------------
extern "C" void kernel_launch(void* const* d_in, const int* in_sizes, int n_in,
                              void* d_out, int out_size) {
    const float* a     = (const float*)d_in[0];
    const int*   idx   = (const int*)d_in[2];
    const float* W_a   = (const float*)d_in[3];
    const float* W_out = (const float*)d_in[4];
    const float* W_cl  = (const float*)d_in[5];
    const float* W_cm  = (const float*)d_in[6];
    const float* Wm1   = (const float*)d_in[7];
    const float* Wm2   = (const float*)d_in[8];
    const float* W_pb  = (const float*)d_in[9];
    const float* Wq    = (const float*)d_in[10];
    const float* Wk    = (const float*)d_in[11];
    const float* Wv    = (const float*)d_in[12];
    const float* Wo    = (const float*)d_in[13];
    const float* ln1g  = (const float*)d_in[14];
    const float* ln1b  = (const float*)d_in[15];
    const float* Wt1   = (const float*)d_in[16];
    const float* Wt2   = (const float*)d_in[17];
    const float* ln2g  = (const float*)d_in[18];
    const float* ln2b  = (const float*)d_in[19];
    float* out = (float*)d_out;

    float *x, *h, *q, *k, *v, *o, *hid, *atok, *bias;
    cudaGetSymbolAddress((void**)&x, g_x);
    cudaGetSymbolAddress((void**)&h, g_h);
    cudaGetSymbolAddress((void**)&q, g_q);
    cudaGetSymbolAddress((void**)&k, g_k);
    cudaGetSymbolAddress((void**)&v, g_v);
    cudaGetSymbolAddress((void**)&o, g_o);
    cudaGetSymbolAddress((void**)&hid, g_hid);
    cudaGetSymbolAddress((void**)&atok, g_atok);
    cudaGetSymbolAddress((void**)&bias, g_bias);

    const int Mrows = NB * NATOMS;  // 65536

    // 1) token projection + gather
    sgemm_kernel<<<dim3(128 / 64, (NB * NTOK) / 64), 256>>>(a, W_a, nullptr, atok,
                                                            NB * NTOK, CATOM, CTOK, 0);
    {
        size_t tot = (size_t)NB * NATOMS * CATOM;
        gather_kernel<<<(unsigned)((tot + 255) / 256), 256>>>(atok, idx, x);
    }

    // 2) pair embedding -> attention bias (uses pre-block x)
    pair_kernel<<<NB, 128>>>(x, W_cl, W_cm, Wm1, Wm2, W_pb, bias);

    // 3) transformer blocks
    for (int l = 0; l < 3; l++) {
        const float* wq = Wq + (size_t)l * CATOM * CATOM;
        const float* wk = Wk + (size_t)l * CATOM * CATOM;
        const float* wv = Wv + (size_t)l * CATOM * CATOM;
        const float* wo = Wo + (size_t)l * CATOM * CATOM;
        const float* wt1 = Wt1 + (size_t)l * CATOM * 512;
        const float* wt2 = Wt2 + (size_t)l * 512 * CATOM;

        ln_kernel<<<Mrows, 128>>>(x, h, ln1g + l * 128, ln1b + l * 128);
        sgemm_kernel<<<dim3(2, Mrows / 64), 256>>>(h, wq, nullptr, q, Mrows, 128, 128, 0);
        sgemm_kernel<<<dim3(2, Mrows / 64), 256>>>(h, wk, nullptr, k, Mrows, 128, 128, 0);
        sgemm_kernel<<<dim3(2, Mrows / 64), 256>>>(h, wv, nullptr, v, Mrows, 128, 128, 0);
        attn_kernel<<<NB * NWIN, 256>>>(q, k, v, bias, o);
        sgemm_kernel<<<dim3(2, Mrows / 64), 256>>>(o, wo, x, x, Mrows, 128, 128, 2);
        ln_kernel<<<Mrows, 128>>>(x, h, ln2g + l * 128, ln2b + l * 128);
        sgemm_kernel<<<dim3(8, Mrows / 64), 256>>>(h, wt1, nullptr, hid, Mrows, 512, 128, 1);
        sgemm_kernel<<<dim3(2, Mrows / 64), 256>>>(hid, wt2, x, x, Mrows, 128, 512, 2);
    }

    // 4) final projection -> output
    sgemm_kernel<<<dim3(2, Mrows / 64), 256>>>(x, W_out, nullptr, out, Mrows, 128, 128, 0);
}

// round 3
// speedup vs baseline: 1.0817x; 1.0817x over previous
#include <cuda_runtime.h>
#include <cuda_bf16.h>
#include <math.h>

#define NB 4
#define NTOK 2048
#define NATOMS 16384
#define CATOM 128
#define CTOK 384
#define CPAIR 16
#define NQ 32
#define NKEY 128
#define NHEADS 4
#define DH 32
#define NWIN (NATOMS / NQ)   // 512
#define PAD 48

// ---------------- scratch (static device globals; no allocation) -------------
__device__ float g_x[NB * NATOMS * CATOM];
__device__ float g_h[NB * NATOMS * CATOM];
__device__ float g_qkv[NB * NATOMS * 384];
__device__ float g_o[NB * NATOMS * CATOM];
__device__ float g_hid[NB * NATOMS * 512];
__device__ float g_atok[NB * NTOK * CATOM];
__device__ float g_bias[NB * NHEADS * NQ * NKEY];
__device__ float g_wqkv[3 * 128 * 384];

// ---------------- helpers ----------------------------------------------------
__device__ __forceinline__ float tf32r(float x) {
    float y;
    asm("cvt.rna.tf32.f32 %0, %1;" : "=f"(y) : "f"(x));
    return y;
}
__device__ __forceinline__ void mma_tf32(float* c, const unsigned* a, const unsigned* b) {
    asm volatile(
        "mma.sync.aligned.m16n8k8.row.col.f32.tf32.tf32.f32 "
        "{%0,%1,%2,%3}, {%4,%5,%6,%7}, {%8,%9}, {%0,%1,%2,%3};"
        : "+f"(c[0]), "+f"(c[1]), "+f"(c[2]), "+f"(c[3])
        : "r"(a[0]), "r"(a[1]), "r"(a[2]), "r"(a[3]), "r"(b[0]), "r"(b[1]));
}

// ---------------- 3xTF32 tensor-core GEMM ------------------------------------
// C[M,N] = [relu]( A[M,K] @ B[K,N] ) [+ Cin]; BM=BN=128, BK=16, 256 threads.
// Accuracy: hi/lo split, c += ah*bh + ah*bl + al*bh  (near-fp32)
// flags: bit0 = relu, bit1 = add Cin
#define BM 128
#define BN 128
#define BK 16
__global__ void __launch_bounds__(256)
gemm3_tf32(const float* __restrict__ A, const float* __restrict__ B,
           const float* __restrict__ Cin, float* __restrict__ C,
           int M, int N, int K, int flags) {
    __shared__ float Ah[BM][BK + 1];
    __shared__ float Al[BM][BK + 1];
    __shared__ float Bh[BK][BN + 4];
    __shared__ float Bl[BK][BN + 4];
    int tid = threadIdx.x;
    int wid = tid >> 5, lane = tid & 31;
    int wm = wid >> 2, wn = wid & 3;       // warp tile: rows wm*64, cols wn*32
    int g = lane >> 2, tg = lane & 3;
    int bx = blockIdx.x, by = blockIdx.y;
    const float* Ag = A + (size_t)by * BM * K;
    const float* Bg = B + (size_t)bx * BN;
    float c[4][4][4] = {};

    for (int kt = 0; kt < K; kt += BK) {
        // A tile: 128x16 = 512 float4 over 256 threads
#pragma unroll
        for (int i = 0; i < 2; i++) {
            int e = tid + 256 * i;
            int r = e >> 2, cc = (e & 3) * 4;
            float4 va = *(const float4*)(Ag + (size_t)r * K + kt + cc);
            float h0 = tf32r(va.x), h1 = tf32r(va.y), h2 = tf32r(va.z), h3 = tf32r(va.w);
            Ah[r][cc] = h0; Ah[r][cc + 1] = h1; Ah[r][cc + 2] = h2; Ah[r][cc + 3] = h3;
            Al[r][cc]     = tf32r(va.x - h0);
            Al[r][cc + 1] = tf32r(va.y - h1);
            Al[r][cc + 2] = tf32r(va.z - h2);
            Al[r][cc + 3] = tf32r(va.w - h3);
        }
        // B tile: 16x128 = 512 float4 over 256 threads
#pragma unroll
        for (int i = 0; i < 2; i++) {
            int e = tid + 256 * i;
            int kk = e >> 5, nv = (e & 31) * 4;
            float4 vb = *(const float4*)(Bg + (size_t)(kt + kk) * N + nv);
            float h0 = tf32r(vb.x), h1 = tf32r(vb.y), h2 = tf32r(vb.z), h3 = tf32r(vb.w);
            Bh[kk][nv] = h0; Bh[kk][nv + 1] = h1; Bh[kk][nv + 2] = h2; Bh[kk][nv + 3] = h3;
            Bl[kk][nv]     = tf32r(vb.x - h0);
            Bl[kk][nv + 1] = tf32r(vb.y - h1);
            Bl[kk][nv + 2] = tf32r(vb.z - h2);
            Bl[kk][nv + 3] = tf32r(vb.w - h3);
        }
        __syncthreads();
#pragma unroll
        for (int ks = 0; ks < BK; ks += 8) {
            unsigned ah[4][4], al[4][4], bh[4][2], bl[4][2];
#pragma unroll
            for (int i = 0; i < 4; i++) {
                int row = wm * 64 + i * 16;
                ah[i][0] = __float_as_uint(Ah[row + g][ks + tg]);
                ah[i][1] = __float_as_uint(Ah[row + g + 8][ks + tg]);
                ah[i][2] = __float_as_uint(Ah[row + g][ks + tg + 4]);
                ah[i][3] = __float_as_uint(Ah[row + g + 8][ks + tg + 4]);
                al[i][0] = __float_as_uint(Al[row + g][ks + tg]);
                al[i][1] = __float_as_uint(Al[row + g + 8][ks + tg]);
                al[i][2] = __float_as_uint(Al[row + g][ks + tg + 4]);
                al[i][3] = __float_as_uint(Al[row + g + 8][ks + tg + 4]);
            }
#pragma unroll
            for (int j = 0; j < 4; j++) {
                int col = wn * 32 + j * 8;
                bh[j][0] = __float_as_uint(Bh[ks + tg][col + g]);
                bh[j][1] = __float_as_uint(Bh[ks + tg + 4][col + g]);
                bl[j][0] = __float_as_uint(Bl[ks + tg][col + g]);
                bl[j][1] = __float_as_uint(Bl[ks + tg + 4][col + g]);
            }
#pragma unroll
            for (int i = 0; i < 4; i++)
#pragma unroll
                for (int j = 0; j < 4; j++) {
                    mma_tf32(c[i][j], ah[i], bl[j]);
                    mma_tf32(c[i][j], al[i], bh[j]);
                    mma_tf32(c[i][j], ah[i], bh[j]);
                }
        }
        __syncthreads();
    }
    // epilogue
#pragma unroll
    for (int i = 0; i < 4; i++) {
        int r0 = by * BM + wm * 64 + i * 16 + g;
#pragma unroll
        for (int j = 0; j < 4; j++) {
            int c0 = bx * BN + wn * 32 + j * 8 + 2 * tg;
#pragma unroll
            for (int t = 0; t < 4; t++) {
                int r = r0 + (t >> 1) * 8;
                int cc = c0 + (t & 1);
                float val = c[i][j][t];
                if (flags & 1) val = fmaxf(val, 0.f);
                size_t idx = (size_t)r * N + cc;
                if (flags & 2) val += Cin[idx];
                C[idx] = val;
            }
        }
    }
}

// ---------------- pack Wq/Wk/Wv into [3][128][384] ---------------------------
__global__ void pack_qkv_kernel(const float* __restrict__ Wq, const float* __restrict__ Wk,
                                const float* __restrict__ Wv, float* __restrict__ Wqkv) {
    int e = blockIdx.x * blockDim.x + threadIdx.x;
    if (e >= 3 * 128 * 384) return;
    int l = e / (128 * 384);
    int rem = e - l * (128 * 384);
    int k = rem / 384, n = rem - k * 384;
    const float* src = (n < 128) ? Wq : (n < 256) ? Wk : Wv;
    Wqkv[e] = src[(size_t)l * 128 * 128 + (size_t)k * 128 + (n & 127)];
}

// ---------------- gather token features to atoms -----------------------------
__global__ void gather_kernel(const float* __restrict__ atok, const int* __restrict__ idx,
                              float* __restrict__ x) {
    size_t i = (size_t)blockIdx.x * blockDim.x + threadIdx.x;
    if (i >= (size_t)NB * NATOMS * CATOM) return;
    int c = (int)(i & 127);
    size_t n = i >> 7;
    int b = (int)(n >> 14);
    int atom = (int)(n & (NATOMS - 1));
    int tok = idx[(size_t)b * NATOMS + atom];
    x[i] = atok[((size_t)b * NTOK + tok) * CATOM + c];
}

// ---------------- layernorm: warp-per-row, float4 ----------------------------
__global__ void ln_kernel(const float* __restrict__ x, float* __restrict__ out,
                          const float* __restrict__ gw, const float* __restrict__ bw) {
    int row = blockIdx.x * 8 + (threadIdx.x >> 5);
    int lane = threadIdx.x & 31;
    const float4* xr = (const float4*)(x + (size_t)row * 128);
    float4 v = xr[lane];
    float s = v.x + v.y + v.z + v.w;
    float s2 = v.x * v.x + v.y * v.y + v.z * v.z + v.w * v.w;
#pragma unroll
    for (int o = 16; o > 0; o >>= 1) {
        s += __shfl_xor_sync(0xffffffff, s, o);
        s2 += __shfl_xor_sync(0xffffffff, s2, o);
    }
    float mean = s * (1.f / 128.f);
    float var = s2 * (1.f / 128.f) - mean * mean;
    float rs = rsqrtf(var + 1e-5f);
    float4 gg = ((const float4*)gw)[lane];
    float4 bb = ((const float4*)bw)[lane];
    float4 o4;
    o4.x = (v.x - mean) * rs * gg.x + bb.x;
    o4.y = (v.y - mean) * rs * gg.y + bb.y;
    o4.z = (v.z - mean) * rs * gg.z + bb.z;
    o4.w = (v.w - mean) * rs * gg.w + bb.w;
    ((float4*)(out + (size_t)row * 128))[lane] = o4;
}

// ---------------- pair embedding + attention bias ----------------------------
__global__ void pair_kernel(const float* __restrict__ x,
                            const float* __restrict__ Wcl, const float* __restrict__ Wcm,
                            const float* __restrict__ Wm1, const float* __restrict__ Wm2,
                            const float* __restrict__ Wpb, float* __restrict__ bias) {
    int b = blockIdx.x;
    int t = threadIdx.x;  // 128
    __shared__ float Wsum[128][16];
    __shared__ float m1[16][16], m2[16][16], pb[16][4];
    __shared__ float p_s[128][17];
    for (int e = t; e < 128 * 16; e += 128) Wsum[e >> 4][e & 15] = Wcl[e] + Wcm[e];
    if (t < 128) {
        if (t < 16 * 16) { m1[t >> 4][t & 15] = Wm1[t]; m2[t >> 4][t & 15] = Wm2[t]; }
        if (t < 64) pb[t >> 2][t & 3] = Wpb[t];
    }
    __syncthreads();
    const float* xr = x + ((size_t)b * NATOMS + t) * 128;
    float t0[16], t1[16];
    for (int c = 0; c < 16; c++) {
        float s = 0.f;
        for (int kk = 0; kk < 128; kk++) s += xr[kk] * Wsum[kk][c];
        t0[c] = s;
    }
    for (int c = 0; c < 16; c++) {
        float s = 0.f;
#pragma unroll
        for (int kk = 0; kk < 16; kk++) s += fmaxf(t0[kk], 0.f) * m1[kk][c];
        t1[c] = s;
    }
    for (int c = 0; c < 16; c++) {
        float s = 0.f;
#pragma unroll
        for (int kk = 0; kk < 16; kk++) s += fmaxf(t1[kk], 0.f) * m2[kk][c];
        p_s[t][c] = s;
    }
    __syncthreads();
    for (int e = t; e < NHEADS * NQ * NKEY; e += 128) {
        int h = e >> 12;
        int qk = e & 4095;
        int qi = qk >> 7, j = qk & 127;
        float s = 0.f;
#pragma unroll
        for (int c = 0; c < 16; c++) s += (p_s[qi][c] + p_s[j][c]) * pb[c][h];
        bias[((size_t)b * NHEADS + h) * 4096 + qk] = s;
    }
}

// ---------------- windowed attention (reads packed qkv, stride 384) ----------
__global__ void attn_kernel(const float* __restrict__ qkv, const float* __restrict__ bias,
                            float* __restrict__ o) {
    int bw = blockIdx.x;
    int b = bw >> 9, w = bw & (NWIN - 1);
    int tid = threadIdx.x;  // 256
    __shared__ float q_s[32][33];
    __shared__ float kv_s[128][33];
    __shared__ float sc[32][128];
    const float scale = 0.17677669529663687f;  // 1/sqrt(32)
    size_t base = (size_t)b * NATOMS * 384;
    size_t obase = (size_t)b * NATOMS * 128;
    int a0 = w * 32 - PAD;
    for (int h = 0; h < NHEADS; h++) {
        for (int e = tid; e < 32 * 32; e += 256) {
            int qi = e >> 5, d = e & 31;
            q_s[qi][d] = qkv[base + (size_t)(w * 32 + qi) * 384 + h * 32 + d];
        }
        for (int e = tid; e < 128 * 32; e += 256) {
            int j = e >> 5, d = e & 31;
            int a = a0 + j;
            kv_s[j][d] = (a >= 0 && a < NATOMS)
                             ? qkv[base + (size_t)a * 384 + 128 + h * 32 + d] : 0.f;
        }
        __syncthreads();
        {
            int qi = tid >> 3, gq = tid & 7;
            const float* brow = bias + (((size_t)b * NHEADS + h) * 32 + qi) * 128;
            for (int j = gq * 16; j < gq * 16 + 16; j++) {
                float s = 0.f;
#pragma unroll
                for (int d = 0; d < 32; d++) s += q_s[qi][d] * kv_s[j][d];
                int a = a0 + j;
                s = s * scale + brow[j];
                if (a < 0 || a >= NATOMS) s = -1e9f;
                sc[qi][j] = s;
            }
        }
        __syncthreads();
        if (tid < 32) {
            float m = -1e30f;
            for (int j = 0; j < 128; j++) m = fmaxf(m, sc[tid][j]);
            float sum = 0.f;
            for (int j = 0; j < 128; j++) {
                float e = expf(sc[tid][j] - m);
                sc[tid][j] = e;
                sum += e;
            }
            float inv = 1.f / sum;
            for (int j = 0; j < 128; j++) sc[tid][j] *= inv;
        }
        __syncthreads();
        for (int e = tid; e < 128 * 32; e += 256) {
            int j = e >> 5, d = e & 31;
            int a = a0 + j;
            kv_s[j][d] = (a >= 0 && a < NATOMS)
                             ? qkv[base + (size_t)a * 384 + 256 + h * 32 + d] : 0.f;
        }
        __syncthreads();
        {
            int qi = tid >> 3, gq = tid & 7;
            float acc[4] = {0.f, 0.f, 0.f, 0.f};
            for (int j = 0; j < 128; j++) {
                float p = sc[qi][j];
#pragma unroll
                for (int dd = 0; dd < 4; dd++) acc[dd] += p * kv_s[j][gq * 4 + dd];
            }
#pragma unroll
            for (int dd = 0; dd < 4; dd++)
                o[obase + (size_t)(w * 32 + qi) * 128 + h * 32 + gq * 4 + dd] = acc[dd];
        }
        __syncthreads();
    }
}

// ---------------- host orchestration -----------------------------------------
extern "C" void kernel_launch(void* const* d_in, const int* in_sizes, int n_in,
                              void* d_out, int out_size) {
    const float* a     = (const float*)d_in[0];
    const int*   idx   = (const int*)d_in[2];
    const float* W_a   = (const float*)d_in[3];
    const float* W_out = (const float*)d_in[4];
    const float* W_cl  = (const float*)d_in[5];
    const float* W_cm  = (const float*)d_in[6];
    const float* Wm1   = (const float*)d_in[7];
    const float* Wm2   = (const float*)d_in[8];
    const float* W_pb  = (const float*)d_in[9];
    const float* Wq    = (const float*)d_in[10];
    const float* Wk    = (const float*)d_in[11];
    const float* Wv    = (const float*)d_in[12];
    const float* Wo    = (const float*)d_in[13];
    const float* ln1g  = (const float*)d_in[14];
    const float* ln1b  = (const float*)d_in[15];
    const float* Wt1   = (const float*)d_in[16];
    const float* Wt2   = (const float*)d_in[17];
    const float* ln2g  = (const float*)d_in[18];
    const float* ln2b  = (const float*)d_in[19];
    float* out = (float*)d_out;

    float *x, *h, *qkv, *o, *hid, *atok, *bias, *wqkv;
    cudaGetSymbolAddress((void**)&x, g_x);
    cudaGetSymbolAddress((void**)&h, g_h);
    cudaGetSymbolAddress((void**)&qkv, g_qkv);
    cudaGetSymbolAddress((void**)&o, g_o);
    cudaGetSymbolAddress((void**)&hid, g_hid);
    cudaGetSymbolAddress((void**)&atok, g_atok);
    cudaGetSymbolAddress((void**)&bias, g_bias);
    cudaGetSymbolAddress((void**)&wqkv, g_wqkv);

    const int Mrows = NB * NATOMS;  // 65536

    // 0) pack QKV weights
    pack_qkv_kernel<<<(3 * 128 * 384 + 255) / 256, 256>>>(Wq, Wk, Wv, wqkv);

    // 1) token projection + gather
    gemm3_tf32<<<dim3(1, (NB * NTOK) / 128), 256>>>(a, W_a, nullptr, atok,
                                                    NB * NTOK, CATOM, CTOK, 0);
    {
        size_t tot = (size_t)NB * NATOMS * CATOM;
        gather_kernel<<<(unsigned)((tot + 255) / 256), 256>>>(atok, idx, x);
    }

    // 2) pair embedding -> attention bias
    pair_kernel<<<NB, 128>>>(x, W_cl, W_cm, Wm1, Wm2, W_pb, bias);

    // 3) transformer blocks
    for (int l = 0; l < 3; l++) {
        const float* wqkv_l = wqkv + (size_t)l * 128 * 384;
        const float* wo = Wo + (size_t)l * CATOM * CATOM;
        const float* wt1 = Wt1 + (size_t)l * CATOM * 512;
        const float* wt2 = Wt2 + (size_t)l * 512 * CATOM;

        ln_kernel<<<Mrows / 8, 256>>>(x, h, ln1g + l * 128, ln1b + l * 128);
        gemm3_tf32<<<dim3(3, Mrows / 128), 256>>>(h, wqkv_l, nullptr, qkv, Mrows, 384, 128, 0);
        attn_kernel<<<NB * NWIN, 256>>>(qkv, bias, o);
        gemm3_tf32<<<dim3(1, Mrows / 128), 256>>>(o, wo, x, x, Mrows, 128, 128, 2);
        ln_kernel<<<Mrows / 8, 256>>>(x, h, ln2g + l * 128, ln2b + l * 128);
        gemm3_tf32<<<dim3(4, Mrows / 128), 256>>>(h, wt1, nullptr, hid, Mrows, 512, 128, 1);
        gemm3_tf32<<<dim3(1, Mrows / 128), 256>>>(hid, wt2, x, x, Mrows, 128, 512, 2);
    }

    // 4) final projection -> output
    gemm3_tf32<<<dim3(1, Mrows / 128), 256>>>(x, W_out, nullptr, out, Mrows, 128, 128, 0);
}

// round 5
// speedup vs baseline: 2.4072x; 2.2253x over previous
#include <cuda_runtime.h>
#include <cuda_bf16.h>
#include <math.h>

#define NB 4
#define NTOK 2048
#define NATOMS 16384
#define CATOM 128
#define CTOK 384
#define CPAIR 16
#define NQ 32
#define NKEY 128
#define NHEADS 4
#define DH 32
#define NWIN (NATOMS / NQ)   // 512
#define PAD 48

// ---------------- scratch (static device globals; no allocation) -------------
__device__ float g_x[NB * NATOMS * CATOM];
__device__ float g_h[NB * NATOMS * CATOM];
__device__ float g_qkv[NB * NATOMS * 384];
__device__ float g_o[NB * NATOMS * CATOM];
__device__ float g_hid[NB * NATOMS * 512];
__device__ float g_atok[NB * NTOK * CATOM];
__device__ float g_bias[NB * NHEADS * NQ * NKEY];
__device__ float g_wqkv[3 * 128 * 384];
__device__ float g_pair[NB * 128 * 16];

// ---------------- helpers ----------------------------------------------------
__device__ __forceinline__ float tf32r(float x) {
    float y;
    asm("cvt.rna.tf32.f32 %0, %1;" : "=f"(y) : "f"(x));
    return y;
}
__device__ __forceinline__ void mma_tf32(float* c, const unsigned* a, const unsigned* b) {
    asm volatile(
        "mma.sync.aligned.m16n8k8.row.col.f32.tf32.tf32.f32 "
        "{%0,%1,%2,%3}, {%4,%5,%6,%7}, {%8,%9}, {%0,%1,%2,%3};"
        : "+f"(c[0]), "+f"(c[1]), "+f"(c[2]), "+f"(c[3])
        : "r"(a[0]), "r"(a[1]), "r"(a[2]), "r"(a[3]), "r"(b[0]), "r"(b[1]));
}

// ---------------- 3xTF32 tensor-core GEMM with reg-prefetch ------------------
// C[M,N] = [relu]( A[M,K] @ B[K,N] ) [+ Cin]; BM=BN=128, BK=16, 256 threads.
// flags: bit0 = relu, bit1 = add Cin
#define BM 128
#define BN 128
#define BK 16
__global__ void __launch_bounds__(256)
gemm3_tf32(const float* __restrict__ A, const float* __restrict__ B,
           const float* __restrict__ Cin, float* __restrict__ C,
           int M, int N, int K, int flags) {
    __shared__ float Ah[BM][BK + 1];
    __shared__ float Al[BM][BK + 1];
    __shared__ float Bh[BK][BN + 4];
    __shared__ float Bl[BK][BN + 4];
    int tid = threadIdx.x;
    int wid = tid >> 5, lane = tid & 31;
    int wm = wid >> 2, wn = wid & 3;
    int g = lane >> 2, tg = lane & 3;
    int bx = blockIdx.x, by = blockIdx.y;
    const float* Ag = A + (size_t)by * BM * K;
    const float* Bg = B + (size_t)bx * BN;
    float c[4][4][4] = {};

    int ar = tid >> 2, acc_ = (tid & 3) * 4;       // A rows ar and ar+64, 4 cols each
    int bk = tid >> 5, bn = (tid & 31) * 4;        // B rows bk and bk+8
    float4 ra0, ra1, rb0, rb1;

    // prologue: load tile 0
    ra0 = *(const float4*)(Ag + (size_t)ar * K + acc_);
    ra1 = *(const float4*)(Ag + (size_t)(ar + 64) * K + acc_);
    rb0 = *(const float4*)(Bg + (size_t)bk * N + bn);
    rb1 = *(const float4*)(Bg + (size_t)(bk + 8) * N + bn);

    int tiles = K / BK;
    for (int t = 0; t < tiles; t++) {
        // store + convert current tile
        {
            float h0 = tf32r(ra0.x), h1 = tf32r(ra0.y), h2 = tf32r(ra0.z), h3 = tf32r(ra0.w);
            Ah[ar][acc_] = h0; Ah[ar][acc_ + 1] = h1; Ah[ar][acc_ + 2] = h2; Ah[ar][acc_ + 3] = h3;
            Al[ar][acc_]     = tf32r(ra0.x - h0);
            Al[ar][acc_ + 1] = tf32r(ra0.y - h1);
            Al[ar][acc_ + 2] = tf32r(ra0.z - h2);
            Al[ar][acc_ + 3] = tf32r(ra0.w - h3);
            float i0 = tf32r(ra1.x), i1 = tf32r(ra1.y), i2 = tf32r(ra1.z), i3 = tf32r(ra1.w);
            Ah[ar + 64][acc_] = i0; Ah[ar + 64][acc_ + 1] = i1;
            Ah[ar + 64][acc_ + 2] = i2; Ah[ar + 64][acc_ + 3] = i3;
            Al[ar + 64][acc_]     = tf32r(ra1.x - i0);
            Al[ar + 64][acc_ + 1] = tf32r(ra1.y - i1);
            Al[ar + 64][acc_ + 2] = tf32r(ra1.z - i2);
            Al[ar + 64][acc_ + 3] = tf32r(ra1.w - i3);
            float p0 = tf32r(rb0.x), p1 = tf32r(rb0.y), p2 = tf32r(rb0.z), p3 = tf32r(rb0.w);
            Bh[bk][bn] = p0; Bh[bk][bn + 1] = p1; Bh[bk][bn + 2] = p2; Bh[bk][bn + 3] = p3;
            Bl[bk][bn]     = tf32r(rb0.x - p0);
            Bl[bk][bn + 1] = tf32r(rb0.y - p1);
            Bl[bk][bn + 2] = tf32r(rb0.z - p2);
            Bl[bk][bn + 3] = tf32r(rb0.w - p3);
            float q0 = tf32r(rb1.x), q1 = tf32r(rb1.y), q2 = tf32r(rb1.z), q3 = tf32r(rb1.w);
            Bh[bk + 8][bn] = q0; Bh[bk + 8][bn + 1] = q1; Bh[bk + 8][bn + 2] = q2; Bh[bk + 8][bn + 3] = q3;
            Bl[bk + 8][bn]     = tf32r(rb1.x - q0);
            Bl[bk + 8][bn + 1] = tf32r(rb1.y - q1);
            Bl[bk + 8][bn + 2] = tf32r(rb1.z - q2);
            Bl[bk + 8][bn + 3] = tf32r(rb1.w - q3);
        }
        __syncthreads();
        // prefetch next tile
        if (t + 1 < tiles) {
            int kt = (t + 1) * BK;
            ra0 = *(const float4*)(Ag + (size_t)ar * K + kt + acc_);
            ra1 = *(const float4*)(Ag + (size_t)(ar + 64) * K + kt + acc_);
            rb0 = *(const float4*)(Bg + (size_t)(kt + bk) * N + bn);
            rb1 = *(const float4*)(Bg + (size_t)(kt + bk + 8) * N + bn);
        }
#pragma unroll
        for (int ks = 0; ks < BK; ks += 8) {
            unsigned ah[4][4], al[4][4], bh[4][2], bl[4][2];
#pragma unroll
            for (int i = 0; i < 4; i++) {
                int row = wm * 64 + i * 16;
                ah[i][0] = __float_as_uint(Ah[row + g][ks + tg]);
                ah[i][1] = __float_as_uint(Ah[row + g + 8][ks + tg]);
                ah[i][2] = __float_as_uint(Ah[row + g][ks + tg + 4]);
                ah[i][3] = __float_as_uint(Ah[row + g + 8][ks + tg + 4]);
                al[i][0] = __float_as_uint(Al[row + g][ks + tg]);
                al[i][1] = __float_as_uint(Al[row + g + 8][ks + tg]);
                al[i][2] = __float_as_uint(Al[row + g][ks + tg + 4]);
                al[i][3] = __float_as_uint(Al[row + g + 8][ks + tg + 4]);
            }
#pragma unroll
            for (int j = 0; j < 4; j++) {
                int col = wn * 32 + j * 8;
                bh[j][0] = __float_as_uint(Bh[ks + tg][col + g]);
                bh[j][1] = __float_as_uint(Bh[ks + tg + 4][col + g]);
                bl[j][0] = __float_as_uint(Bl[ks + tg][col + g]);
                bl[j][1] = __float_as_uint(Bl[ks + tg + 4][col + g]);
            }
#pragma unroll
            for (int i = 0; i < 4; i++)
#pragma unroll
                for (int j = 0; j < 4; j++) {
                    mma_tf32(c[i][j], ah[i], bl[j]);
                    mma_tf32(c[i][j], al[i], bh[j]);
                    mma_tf32(c[i][j], ah[i], bh[j]);
                }
        }
        __syncthreads();
    }
    // epilogue
#pragma unroll
    for (int i = 0; i < 4; i++) {
        int r0 = by * BM + wm * 64 + i * 16 + g;
#pragma unroll
        for (int j = 0; j < 4; j++) {
            int c0 = bx * BN + wn * 32 + j * 8 + 2 * tg;
#pragma unroll
            for (int t = 0; t < 4; t++) {
                int r = r0 + (t >> 1) * 8;
                int cc = c0 + (t & 1);
                float val = c[i][j][t];
                if (flags & 1) val = fmaxf(val, 0.f);
                size_t idx = (size_t)r * N + cc;
                if (flags & 2) val += Cin[idx];
                C[idx] = val;
            }
        }
    }
}

// ---------------- pack Wq/Wk/Wv into [3][128][384] ---------------------------
__global__ void pack_qkv_kernel(const float* __restrict__ Wq, const float* __restrict__ Wk,
                                const float* __restrict__ Wv, float* __restrict__ Wqkv) {
    int e = blockIdx.x * blockDim.x + threadIdx.x;
    if (e >= 3 * 128 * 384) return;
    int l = e / (128 * 384);
    int rem = e - l * (128 * 384);
    int k = rem / 384, n = rem - k * 384;
    const float* src = (n < 128) ? Wq : (n < 256) ? Wk : Wv;
    Wqkv[e] = src[(size_t)l * 128 * 128 + (size_t)k * 128 + (n & 127)];
}

// ---------------- gather token features to atoms -----------------------------
__global__ void gather_kernel(const float* __restrict__ atok, const int* __restrict__ idx,
                              float* __restrict__ x) {
    size_t i = (size_t)blockIdx.x * blockDim.x + threadIdx.x;
    if (i >= (size_t)NB * NATOMS * CATOM) return;
    int c = (int)(i & 127);
    size_t n = i >> 7;
    int b = (int)(n >> 14);
    int atom = (int)(n & (NATOMS - 1));
    int tok = idx[(size_t)b * NATOMS + atom];
    x[i] = atok[((size_t)b * NTOK + tok) * CATOM + c];
}

// ---------------- layernorm: warp-per-row, float4 ----------------------------
__global__ void ln_kernel(const float* __restrict__ x, float* __restrict__ out,
                          const float* __restrict__ gw, const float* __restrict__ bw) {
    int row = blockIdx.x * 8 + (threadIdx.x >> 5);
    int lane = threadIdx.x & 31;
    const float4* xr = (const float4*)(x + (size_t)row * 128);
    float4 v = xr[lane];
    float s = v.x + v.y + v.z + v.w;
    float s2 = v.x * v.x + v.y * v.y + v.z * v.z + v.w * v.w;
#pragma unroll
    for (int o = 16; o > 0; o >>= 1) {
        s += __shfl_xor_sync(0xffffffff, s, o);
        s2 += __shfl_xor_sync(0xffffffff, s2, o);
    }
    float mean = s * (1.f / 128.f);
    float var = s2 * (1.f / 128.f) - mean * mean;
    float rs = rsqrtf(var + 1e-5f);
    float4 gg = ((const float4*)gw)[lane];
    float4 bb = ((const float4*)bw)[lane];
    float4 o4;
    o4.x = (v.x - mean) * rs * gg.x + bb.x;
    o4.y = (v.y - mean) * rs * gg.y + bb.y;
    o4.z = (v.z - mean) * rs * gg.z + bb.z;
    o4.w = (v.w - mean) * rs * gg.w + bb.w;
    ((float4*)(out + (size_t)row * 128))[lane] = o4;
}

// ---------------- pair stage 1: p_s for atoms [0,128) per batch --------------
__global__ void __launch_bounds__(512)
pair_p_kernel(const float* __restrict__ x,
              const float* __restrict__ Wcl, const float* __restrict__ Wcm,
              const float* __restrict__ Wm1, const float* __restrict__ Wm2,
              float* __restrict__ pair_out) {
    int b = blockIdx.x;
    int t = threadIdx.x;
    __shared__ float Wsum[128][17];
    __shared__ float m1[16][16], m2[16][16];
    __shared__ float t0s[128][17], t1s[128][17];
    for (int e = t; e < 128 * 16; e += 512) Wsum[e >> 4][e & 15] = Wcl[e] + Wcm[e];
    if (t < 256) m1[t >> 4][t & 15] = Wm1[t];
    else if (t < 512) m2[(t - 256) >> 4][(t - 256) & 15] = Wm2[t - 256];
    __syncthreads();
    int atom = t >> 2, cg = (t & 3) * 4;
    const float4* xr = (const float4*)(x + ((size_t)b * NATOMS + atom) * 128);
    float s[4] = {0.f, 0.f, 0.f, 0.f};
    for (int k4 = 0; k4 < 32; k4++) {
        float4 xv = xr[k4];
#pragma unroll
        for (int c = 0; c < 4; c++) {
            s[c] += xv.x * Wsum[k4 * 4 + 0][cg + c];
            s[c] += xv.y * Wsum[k4 * 4 + 1][cg + c];
            s[c] += xv.z * Wsum[k4 * 4 + 2][cg + c];
            s[c] += xv.w * Wsum[k4 * 4 + 3][cg + c];
        }
    }
#pragma unroll
    for (int c = 0; c < 4; c++) t0s[atom][cg + c] = s[c];
    __syncthreads();
    float s2[4] = {0.f, 0.f, 0.f, 0.f};
#pragma unroll
    for (int k = 0; k < 16; k++) {
        float r = fmaxf(t0s[atom][k], 0.f);
#pragma unroll
        for (int c = 0; c < 4; c++) s2[c] += r * m1[k][cg + c];
    }
#pragma unroll
    for (int c = 0; c < 4; c++) t1s[atom][cg + c] = s2[c];
    __syncthreads();
    float s3[4] = {0.f, 0.f, 0.f, 0.f};
#pragma unroll
    for (int k = 0; k < 16; k++) {
        float r = fmaxf(t1s[atom][k], 0.f);
#pragma unroll
        for (int c = 0; c < 4; c++) s3[c] += r * m2[k][cg + c];
    }
#pragma unroll
    for (int c = 0; c < 4; c++)
        pair_out[((size_t)b * 128 + atom) * 16 + cg + c] = s3[c];
}

// ---------------- pair stage 2: bias[b,h,qi,j] -------------------------------
__global__ void bias_kernel(const float* __restrict__ pair_in,
                            const float* __restrict__ Wpb, float* __restrict__ bias) {
    int b = blockIdx.x >> 4, chunk = blockIdx.x & 15;
    int t = threadIdx.x;
    __shared__ float ps[128][17];
    __shared__ float pb[16][4];
    for (int e = t; e < 128 * 16; e += 256) ps[e >> 4][e & 15] = pair_in[(size_t)b * 2048 + e];
    if (t < 64) pb[t >> 2][t & 3] = Wpb[t];
    __syncthreads();
#pragma unroll
    for (int u = 0; u < 4; u++) {
        int e = chunk * 1024 + t + 256 * u;
        int h = e >> 12;
        int qk = e & 4095;
        int qi = qk >> 7, j = qk & 127;
        float s = 0.f;
#pragma unroll
        for (int c = 0; c < 16; c++) s += (ps[qi][c] + ps[j][c]) * pb[c][h];
        bias[(size_t)b * 16384 + e] = s;
    }
}

// ---------------- windowed attention: block per (b, w, head) -----------------
__global__ void __launch_bounds__(128)
attn_kernel(const float* __restrict__ qkv, const float* __restrict__ bias,
            float* __restrict__ o) {
    int bwh = blockIdx.x;
    int h = bwh & 3;
    int w = (bwh >> 2) & (NWIN - 1);
    int b = bwh >> 11;
    int tid = threadIdx.x;
    int wi = tid >> 5, lane = tid & 31;
    __shared__ float q_s[32][36];
    __shared__ float kv_s[128][36];
    __shared__ float sc[32][129];
    const float scale = 0.17677669529663687f;
    size_t base = (size_t)b * NATOMS * 384;
    size_t obase = (size_t)b * NATOMS * 128;
    int a0 = w * 32 - PAD;

#pragma unroll
    for (int i = 0; i < 2; i++) {
        int e = tid + 128 * i;
        int r = e >> 3, c4 = e & 7;
        float4 v = *(const float4*)(qkv + base + (size_t)(w * 32 + r) * 384 + h * 32 + c4 * 4);
        *(float4*)(&q_s[r][c4 * 4]) = v;
    }
#pragma unroll
    for (int i = 0; i < 8; i++) {
        int e = tid + 128 * i;
        int r = e >> 3, c4 = e & 7;
        int a = a0 + r;
        float4 v = make_float4(0.f, 0.f, 0.f, 0.f);
        if (a >= 0 && a < NATOMS)
            v = *(const float4*)(qkv + base + (size_t)a * 384 + 128 + h * 32 + c4 * 4);
        *(float4*)(&kv_s[r][c4 * 4]) = v;
    }
    __syncthreads();

    const float* bb = bias + (((size_t)b * NHEADS + h) * 32) * 128;
#pragma unroll
    for (int rr = 0; rr < 8; rr++) {
        int r = wi * 8 + rr;
        float s[4];
#pragma unroll
        for (int c = 0; c < 4; c++) {
            int j = lane + 32 * c;
            float acc = 0.f;
            const float4* qrow = (const float4*)q_s[r];
            const float4* krow = (const float4*)kv_s[j];
#pragma unroll
            for (int d4 = 0; d4 < 8; d4++) {
                float4 qq = qrow[d4];
                float4 kk = krow[d4];
                acc += qq.x * kk.x + qq.y * kk.y + qq.z * kk.z + qq.w * kk.w;
            }
            int a = a0 + j;
            s[c] = acc * scale + bb[r * 128 + j];
            if (a < 0 || a >= NATOMS) s[c] = -1e9f;
        }
        float m = fmaxf(fmaxf(s[0], s[1]), fmaxf(s[2], s[3]));
#pragma unroll
        for (int off = 16; off > 0; off >>= 1)
            m = fmaxf(m, __shfl_xor_sync(0xffffffff, m, off));
        float sum = 0.f;
#pragma unroll
        for (int c = 0; c < 4; c++) {
            s[c] = __expf(s[c] - m);
            sum += s[c];
        }
#pragma unroll
        for (int off = 16; off > 0; off >>= 1)
            sum += __shfl_xor_sync(0xffffffff, sum, off);
        float inv = 1.f / sum;
#pragma unroll
        for (int c = 0; c < 4; c++) sc[r][lane + 32 * c] = s[c] * inv;
    }
    __syncthreads();

#pragma unroll
    for (int i = 0; i < 8; i++) {
        int e = tid + 128 * i;
        int r = e >> 3, c4 = e & 7;
        int a = a0 + r;
        float4 v = make_float4(0.f, 0.f, 0.f, 0.f);
        if (a >= 0 && a < NATOMS)
            v = *(const float4*)(qkv + base + (size_t)a * 384 + 256 + h * 32 + c4 * 4);
        *(float4*)(&kv_s[r][c4 * 4]) = v;
    }
    __syncthreads();

    {
        int r = tid >> 2, dg = tid & 3;
        float4 acc0 = make_float4(0.f, 0.f, 0.f, 0.f);
        float4 acc1 = make_float4(0.f, 0.f, 0.f, 0.f);
        for (int j = 0; j < 128; j++) {
            float p = sc[r][j];
            const float4* vrow = (const float4*)kv_s[j];
            float4 v0 = vrow[dg * 2];
            float4 v1 = vrow[dg * 2 + 1];
            acc0.x += p * v0.x; acc0.y += p * v0.y; acc0.z += p * v0.z; acc0.w += p * v0.w;
            acc1.x += p * v1.x; acc1.y += p * v1.y; acc1.z += p * v1.z; acc1.w += p * v1.w;
        }
        float* op = o + obase + (size_t)(w * 32 + r) * 128 + h * 32 + dg * 8;
        *(float4*)op = acc0;
        *(float4*)(op + 4) = acc1;
    }
}

// ---------------- host orchestration -----------------------------------------
extern "C" void kernel_launch(void* const* d_in, const int* in_sizes, int n_in,
                              void* d_out, int out_size) {
    const float* a     = (const float*)d_in[0];
    const int*   idx   = (const int*)d_in[2];
    const float* W_a   = (const float*)d_in[3];
    const float* W_out = (const float*)d_in[4];
    const float* W_cl  = (const float*)d_in[5];
    const float* W_cm  = (const float*)d_in[6];
    const float* Wm1   = (const float*)d_in[7];
    const float* Wm2   = (const float*)d_in[8];
    const float* W_pb  = (const float*)d_in[9];
    const float* Wq    = (const float*)d_in[10];
    const float* Wk    = (const float*)d_in[11];
    const float* Wv    = (const float*)d_in[12];
    const float* Wo    = (const float*)d_in[13];
    const float* ln1g  = (const float*)d_in[14];
    const float* ln1b  = (const float*)d_in[15];
    const float* Wt1   = (const float*)d_in[16];
    const float* Wt2   = (const float*)d_in[17];
    const float* ln2g  = (const float*)d_in[18];
    const float* ln2b  = (const float*)d_in[19];
    float* out = (float*)d_out;

    float *x, *h, *qkv, *o, *hid, *atok, *bias, *wqkv, *pair;
    cudaGetSymbolAddress((void**)&x, g_x);
    cudaGetSymbolAddress((void**)&h, g_h);
    cudaGetSymbolAddress((void**)&qkv, g_qkv);
    cudaGetSymbolAddress((void**)&o, g_o);
    cudaGetSymbolAddress((void**)&hid, g_hid);
    cudaGetSymbolAddress((void**)&atok, g_atok);
    cudaGetSymbolAddress((void**)&bias, g_bias);
    cudaGetSymbolAddress((void**)&wqkv, g_wqkv);
    cudaGetSymbolAddress((void**)&pair, g_pair);

    const int Mrows = NB * NATOMS;  // 65536

    // 0) pack QKV weights
    pack_qkv_kernel<<<(3 * 128 * 384 + 255) / 256, 256>>>(Wq, Wk, Wv, wqkv);

    // 1) token projection + gather
    gemm3_tf32<<<dim3(1, (NB * NTOK) / 128), 256>>>(a, W_a, nullptr, atok,
                                                    NB * NTOK, CATOM, CTOK, 0);
    {
        size_t tot = (size_t)NB * NATOMS * CATOM;
        gather_kernel<<<(unsigned)((tot + 255) / 256), 256>>>(atok, idx, x);
    }

    // 2) pair embedding -> attention bias
    pair_p_kernel<<<NB, 512>>>(x, W_cl, W_cm, Wm1, Wm2, pair);
    bias_kernel<<<NB * 16, 256>>>(pair, W_pb, bias);

    // 3) transformer blocks
    for (int l = 0; l < 3; l++) {
        const float* wqkv_l = wqkv + (size_t)l * 128 * 384;
        const float* wo = Wo + (size_t)l * CATOM * CATOM;
        const float* wt1 = Wt1 + (size_t)l * CATOM * 512;
        const float* wt2 = Wt2 + (size_t)l * 512 * CATOM;

        ln_kernel<<<Mrows / 8, 256>>>(x, h, ln1g + l * 128, ln1b + l * 128);
        gemm3_tf32<<<dim3(3, Mrows / 128), 256>>>(h, wqkv_l, nullptr, qkv, Mrows, 384, 128, 0);
        attn_kernel<<<NB * NWIN * NHEADS, 128>>>(qkv, bias, o);
        gemm3_tf32<<<dim3(1, Mrows / 128), 256>>>(o, wo, x, x, Mrows, 128, 128, 2);
        ln_kernel<<<Mrows / 8, 256>>>(x, h, ln2g + l * 128, ln2b + l * 128);
        gemm3_tf32<<<dim3(4, Mrows / 128), 256>>>(h, wt1, nullptr, hid, Mrows, 512, 128, 1);
        gemm3_tf32<<<dim3(1, Mrows / 128), 256>>>(hid, wt2, x, x, Mrows, 128, 512, 2);
    }

    // 4) final projection -> output
    gemm3_tf32<<<dim3(1, Mrows / 128), 256>>>(x, W_out, nullptr, out, Mrows, 128, 128, 0);
}